// round 6
// baseline (speedup 1.0000x reference)
#include <cuda_runtime.h>
#include <cstdint>
#include <cstddef>

// 1x1 conv as GEMM on HMMA (mma.sync tf32), sm_103 target (no tcgen05 in the
// harness's compute_103 PTX path).
// out[b,o,p] = sum_i W[i,o] * x[b,i,p];  B=32, CIN=COUT=128, HW=16384.
// R6: 4-stage cp.async pipeline of 16-row B chunks (8KB each, XOR-swizzled),
// wait_group(2), ONE __syncthreads per chunk, inner 8-chunk loop unrolled.
// SMEM = A(69.6KB) + 4x8KB = 101.6KB -> 2 CTAs/SM.
// Tile: M=128(COUT) x N=128(px) x K=128. 8 warps 2(M)x4(N), warp m64n32.

#define HW      16384
#define NCH     128
#define TILE_N  128
#define NTILES  4096
#define GRID    304
#define NTHREADS 256
#define ROWW    136                  // padded A row width (floats)

#define A_OFF   0                    // 128*136 = 17408 floats
#define B_OFF   17408                // 4 chunk buffers x 2048 floats
#define SMEM_FLOATS (17408 + 4 * 2048)
#define SMEM_BYTES  (SMEM_FLOATS * 4)    // 104448 B

__device__ __forceinline__ uint32_t smem_u32(const void* p) {
    uint32_t a;
    asm("{ .reg .u64 t; cvta.to.shared.u64 t, %1; cvt.u32.u64 %0, t; }" : "=r"(a) : "l"(p));
    return a;
}

#define CP_ASYNC16(smaddr, gptr) \
    asm volatile("cp.async.cg.shared.global [%0], [%1], 16;" \
        :: "r"(smaddr), "l"(__cvta_generic_to_global(gptr)) : "memory")
#define CP_COMMIT() asm volatile("cp.async.commit_group;" ::: "memory")
#define CP_WAIT2()  asm volatile("cp.async.wait_group 2;" ::: "memory")

__device__ __forceinline__ void mma_tf32(float c[4], uint32_t a0, uint32_t a1,
                                         uint32_t a2, uint32_t a3,
                                         uint32_t b0, uint32_t b1) {
    asm volatile(
        "mma.sync.aligned.m16n8k8.row.col.f32.tf32.tf32.f32 "
        "{%0,%1,%2,%3},{%4,%5,%6,%7},{%8,%9},{%0,%1,%2,%3};"
        : "+f"(c[0]), "+f"(c[1]), "+f"(c[2]), "+f"(c[3])
        : "r"(a0), "r"(a1), "r"(a2), "r"(a3), "r"(b0), "r"(b1));
}

__global__ __launch_bounds__(NTHREADS, 2)
void conv1x1_hmma_kernel(const float* __restrict__ x,
                         const float* __restrict__ w,
                         float* __restrict__ out)
{
    extern __shared__ __align__(16) float smem[];
    const uint32_t sb = smem_u32(smem);
    const int tid = threadIdx.x;
    const int lid = tid & 31;
    const int wid = tid >> 5;
    const int mw  = wid & 1;          // M half
    const int nw  = wid >> 1;         // N quarter
    const int bid = blockIdx.x;
    const int lr  = lid >> 2;         // 0..7
    const int lc  = lid & 3;          // 0..3

    // ---- W^T -> A smem once, RN-rounded tf32, k-pair-interleaved:
    // word(o,k) = o*ROWW + (k/8)*8 + (k%4)*2 + ((k/4)&1)
    for (int i = tid; i < NCH * NCH; i += NTHREADS) {
        int k = i >> 7, o = i & 127;
        float v = __ldg(&w[k * NCH + o]);
        uint32_t t;
        asm("cvt.rna.tf32.f32 %0, %1;" : "=r"(t) : "f"(v));
        smem[A_OFF + o * ROWW + (k >> 3) * 8 + (k & 3) * 2 + ((k >> 2) & 1)] = __uint_as_float(t);
    }
    __syncthreads();

    const int n     = (NTILES - bid + GRID - 1) / GRID;
    const int total = 8 * n;          // 16-row chunks

    // ---- chunk loader: 16 k-rows x 128 px, swizzle col ^= (row&3)<<3
    auto load_chunk = [&](int g) {
        int t  = bid + (g >> 3) * GRID;
        int b  = t >> 7;
        int p0 = (t & 127) * TILE_N;
        int k0 = (g & 7) * 16;
        const float* xb = x + ((size_t)b * NCH + k0) * HW + p0;
        uint32_t base = sb + (uint32_t)(B_OFF + (g & 3) * 2048) * 4u;
        #pragma unroll
        for (int j = 0; j < 2; j++) {
            int id  = tid + j * NTHREADS;      // 0..511
            int row = id >> 5;                 // 0..15
            int px4 = (id & 31) * 4;
            uint32_t wd = (uint32_t)(row * 128 + (px4 ^ ((row & 3) << 3)));
            CP_ASYNC16(base + wd * 4u, xb + (size_t)row * HW + px4);
        }
    };

    load_chunk(0); CP_COMMIT();
    load_chunk(1); CP_COMMIT();
    load_chunk(2); CP_COMMIT();

    const float* Asm = smem + A_OFF + (mw * 64 + lr) * ROWW + lc * 2;

    #pragma unroll 1
    for (int i = 0; i < n; i++) {
        float acc[4][4][4];
        #pragma unroll
        for (int mt = 0; mt < 4; mt++)
            #pragma unroll
            for (int nt = 0; nt < 4; nt++)
                #pragma unroll
                for (int q = 0; q < 4; q++) acc[mt][nt][q] = 0.f;

        #pragma unroll
        for (int c8 = 0; c8 < 8; c8++) {
            const int g = i * 8 + c8;
            CP_WAIT2();                 // load(g) resident (issued 3 iters ago)
            __syncthreads();            // all warps see buf; prev compute done

            const float* Bs = smem + B_OFF + (c8 & 3) * 2048 + nw * 32 + lr;

            #pragma unroll
            for (int kl = 0; kl < 2; kl++) {
                const int kk = c8 * 2 + kl;
                uint32_t af[4][4];
                #pragma unroll
                for (int mt = 0; mt < 4; mt++) {
                    const float* pa = Asm + mt * 16 * ROWW + kk * 8;
                    asm volatile("ld.shared.v2.b32 {%0,%1}, [%2];"
                        : "=r"(af[mt][0]), "=r"(af[mt][2]) : "r"(smem_u32(pa)));
                    asm volatile("ld.shared.v2.b32 {%0,%1}, [%2];"
                        : "=r"(af[mt][1]), "=r"(af[mt][3]) : "r"(smem_u32(pa + 8 * ROWW)));
                }
                uint32_t bf[4][2];
                const float* pb = Bs + (kl * 8 + lc) * 128;
                #pragma unroll
                for (int nt = 0; nt < 4; nt++) {
                    int sw = (nt ^ lc) * 8;
                    bf[nt][0] = __float_as_uint(pb[sw]);
                    bf[nt][1] = __float_as_uint(pb[4 * 128 + sw]);
                }
                #pragma unroll
                for (int mt = 0; mt < 4; mt++)
                    #pragma unroll
                    for (int nt = 0; nt < 4; nt++)
                        mma_tf32(acc[mt][nt], af[mt][0], af[mt][1], af[mt][2], af[mt][3],
                                 bf[nt][0], bf[nt][1]);
            }

            // issue next load AFTER compute: buf (g+3)&3 was last read at
            // compute(g-1), which all warps finished before this iteration's
            // barrier -> single barrier per chunk is sufficient.
            if (g + 3 < total) load_chunk(g + 3);
            CP_COMMIT();                // unconditional: keeps group count exact
        }

        // ---- epilogue (overlaps in-flight loads of the next tile)
        {
            int t  = bid + i * GRID;
            int b  = t >> 7;
            int p0 = (t & 127) * TILE_N;
            float* ob = out + (size_t)b * NCH * HW + p0 + nw * 32 + lc * 2;
            #pragma unroll
            for (int mt = 0; mt < 4; mt++) {
                float* orow = ob + (size_t)(mw * 64 + mt * 16 + lr) * HW;
                #pragma unroll
                for (int nt = 0; nt < 4; nt++) {
                    *(float2*)(orow + nt * 8)          = make_float2(acc[mt][nt][0], acc[mt][nt][1]);
                    *(float2*)(orow + 8 * HW + nt * 8) = make_float2(acc[mt][nt][2], acc[mt][nt][3]);
                }
            }
        }
    }
}

extern "C" void kernel_launch(void* const* d_in, const int* in_sizes, int n_in,
                              void* d_out, int out_size)
{
    const float* x = (const float*)d_in[0];   // (32,128,128,128) fp32
    const float* w = (const float*)d_in[1];   // (128,128) fp32
    float* out = (float*)d_out;

    cudaFuncSetAttribute(conv1x1_hmma_kernel,
                         cudaFuncAttributeMaxDynamicSharedMemorySize, SMEM_BYTES);
    conv1x1_hmma_kernel<<<GRID, NTHREADS, SMEM_BYTES>>>(x, w, out);
}

// round 7
// speedup vs baseline: 1.0539x; 1.0539x over previous
#include <cuda_runtime.h>
#include <cstdint>
#include <cstddef>

// 1x1 conv as GEMM on HMMA (mma.sync tf32), sm_103 target (no tcgen05 in the
// harness's compute_103 PTX path).
// out[b,o,p] = sum_i W[i,o] * x[b,i,p];  B=32, CIN=COUT=128, HW=16384.
// R7: R5 structure, but ONE __syncthreads per 32-row chunk and depth-2
// prefetch via 3 rotating B buffers (16KB each). A tile unpadded 64KB with
// XOR swizzle (koff ^= (o&3)<<3) -> total smem 112KB -> 2 CTAs/SM.
// Tile: M=128(COUT) x N=128(px) x K=128. 8 warps 2(M)x4(N), warp m64n32.

#define HW      16384
#define NCH     128
#define TILE_N  128
#define NTILES  4096
#define GRID    304
#define NTHREADS 256

#define A_OFF   0                     // 128*128 = 16384 floats (unpadded, swizzled)
#define B_OFF   16384                 // 3 chunk buffers x 4096 floats (32 rows x 128)
#define SMEM_FLOATS (16384 + 3 * 4096)
#define SMEM_BYTES  (SMEM_FLOATS * 4)     // 114688 B

__device__ __forceinline__ uint32_t smem_u32(const void* p) {
    uint32_t a;
    asm("{ .reg .u64 t; cvta.to.shared.u64 t, %1; cvt.u32.u64 %0, t; }" : "=r"(a) : "l"(p));
    return a;
}

#define CP_ASYNC16(smaddr, gptr) \
    asm volatile("cp.async.cg.shared.global [%0], [%1], 16;" \
        :: "r"(smaddr), "l"(__cvta_generic_to_global(gptr)) : "memory")
#define CP_COMMIT() asm volatile("cp.async.commit_group;" ::: "memory")
#define CP_WAIT1()  asm volatile("cp.async.wait_group 1;" ::: "memory")

__device__ __forceinline__ void mma_tf32(float c[4], uint32_t a0, uint32_t a1,
                                         uint32_t a2, uint32_t a3,
                                         uint32_t b0, uint32_t b1) {
    asm volatile(
        "mma.sync.aligned.m16n8k8.row.col.f32.tf32.tf32.f32 "
        "{%0,%1,%2,%3},{%4,%5,%6,%7},{%8,%9},{%0,%1,%2,%3};"
        : "+f"(c[0]), "+f"(c[1]), "+f"(c[2]), "+f"(c[3])
        : "r"(a0), "r"(a1), "r"(a2), "r"(a3), "r"(b0), "r"(b1));
}

__global__ __launch_bounds__(NTHREADS, 2)
void conv1x1_hmma_kernel(const float* __restrict__ x,
                         const float* __restrict__ w,
                         float* __restrict__ out)
{
    extern __shared__ __align__(16) float smem[];
    const uint32_t sb = smem_u32(smem);
    const int tid = threadIdx.x;
    const int lid = tid & 31;
    const int wid = tid >> 5;
    const int mw  = wid & 1;          // M half
    const int nw  = wid >> 1;         // N quarter
    const int bid = blockIdx.x;
    const int lr  = lid >> 2;         // 0..7
    const int lc  = lid & 3;          // 0..3

    // ---- W^T -> A smem once, RN-rounded tf32.
    // word(o,k) = o*128 + ((k>>3)*8 ^ ((o&3)<<3)) + (k&3)*2 + ((k>>2)&1)
    for (int i = tid; i < NCH * NCH; i += NTHREADS) {
        int k = i >> 7, o = i & 127;
        float v = __ldg(&w[k * NCH + o]);
        uint32_t t;
        asm("cvt.rna.tf32.f32 %0, %1;" : "=r"(t) : "f"(v));
        int wd = o * 128 + (((k >> 3) * 8) ^ ((o & 3) << 3)) + (k & 3) * 2 + ((k >> 2) & 1);
        smem[A_OFF + wd] = __uint_as_float(t);
    }
    __syncthreads();

    const int n     = (NTILES - bid + GRID - 1) / GRID;
    const int total = 4 * n;            // 32-row chunks

    // ---- chunk loader: 32 k-rows x 128 px into buffer lb, col ^= (row&3)<<3
    auto load_chunk = [&](int g, int lb) {
        int t  = bid + (g >> 2) * GRID;
        int b  = t >> 7;
        int p0 = (t & 127) * TILE_N;
        int k0 = (g & 3) * 32;
        const float* xb = x + ((size_t)b * NCH + k0) * HW + p0;
        uint32_t base = sb + (uint32_t)(B_OFF + lb * 4096) * 4u;
        #pragma unroll
        for (int j = 0; j < 4; j++) {
            int id  = tid + j * NTHREADS;      // 0..1023
            int row = id >> 5;                 // 0..31
            int px4 = (id & 31) * 4;
            uint32_t wd = (uint32_t)(row * 128 + (px4 ^ ((row & 3) << 3)));
            CP_ASYNC16(base + wd * 4u, xb + (size_t)row * HW + px4);
        }
    };

    load_chunk(0, 0); CP_COMMIT();
    if (total > 1) load_chunk(1, 1);
    CP_COMMIT();

    const int kxor = (lr & 3) << 3;
    const float* Asm = smem + A_OFF + (mw * 64 + lr) * 128 + lc * 2;
    float acc[4][4][4];

    int cb = 0, lb = 2;                 // compute / load buffer (mod 3)
    #pragma unroll 1
    for (int g = 0; g < total; g++) {
        CP_WAIT1();                     // chunk g resident (this thread's part)
        __syncthreads();                // everyone waited; compute(g-1) done

        if (g + 2 < total) load_chunk(g + 2, lb);
        CP_COMMIT();                    // unconditional: group count stays exact
        lb = (lb == 2) ? 0 : lb + 1;

        if ((g & 3) == 0) {
            #pragma unroll
            for (int mt = 0; mt < 4; mt++)
                #pragma unroll
                for (int nt = 0; nt < 4; nt++)
                    #pragma unroll
                    for (int q = 0; q < 4; q++) acc[mt][nt][q] = 0.f;
        }

        const float* Bs = smem + B_OFF + cb * 4096 + nw * 32 + lr;
        cb = (cb == 2) ? 0 : cb + 1;
        const int kk0 = (g & 3) * 4;

        #pragma unroll
        for (int kl = 0; kl < 4; kl++) {
            const int kk = kk0 + kl;
            uint32_t af[4][4];
            #pragma unroll
            for (int mt = 0; mt < 4; mt++) {
                const float* pa = Asm + mt * 16 * 128 + ((kk * 8) ^ kxor);
                asm volatile("ld.shared.v2.b32 {%0,%1}, [%2];"
                    : "=r"(af[mt][0]), "=r"(af[mt][2]) : "r"(smem_u32(pa)));
                asm volatile("ld.shared.v2.b32 {%0,%1}, [%2];"
                    : "=r"(af[mt][1]), "=r"(af[mt][3]) : "r"(smem_u32(pa + 8 * 128)));
            }
            uint32_t bf[4][2];
            const float* pb = Bs + (kl * 8 + lc) * 128;
            #pragma unroll
            for (int nt = 0; nt < 4; nt++) {
                int sw = (nt ^ lc) * 8;
                bf[nt][0] = __float_as_uint(pb[sw]);
                bf[nt][1] = __float_as_uint(pb[4 * 128 + sw]);
            }
            #pragma unroll
            for (int mt = 0; mt < 4; mt++)
                #pragma unroll
                for (int nt = 0; nt < 4; nt++)
                    mma_tf32(acc[mt][nt], af[mt][0], af[mt][1], af[mt][2], af[mt][3],
                             bf[nt][0], bf[nt][1]);
        }

        if ((g & 3) == 3) {             // tile finished -> epilogue (no barrier)
            int t  = bid + (g >> 2) * GRID;
            int b  = t >> 7;
            int p0 = (t & 127) * TILE_N;
            float* ob = out + (size_t)b * NCH * HW + p0 + nw * 32 + lc * 2;
            #pragma unroll
            for (int mt = 0; mt < 4; mt++) {
                float* orow = ob + (size_t)(mw * 64 + mt * 16 + lr) * HW;
                #pragma unroll
                for (int nt = 0; nt < 4; nt++) {
                    *(float2*)(orow + nt * 8)          = make_float2(acc[mt][nt][0], acc[mt][nt][1]);
                    *(float2*)(orow + 8 * HW + nt * 8) = make_float2(acc[mt][nt][2], acc[mt][nt][3]);
                }
            }
        }
    }
}

extern "C" void kernel_launch(void* const* d_in, const int* in_sizes, int n_in,
                              void* d_out, int out_size)
{
    const float* x = (const float*)d_in[0];   // (32,128,128,128) fp32
    const float* w = (const float*)d_in[1];   // (128,128) fp32
    float* out = (float*)d_out;

    cudaFuncSetAttribute(conv1x1_hmma_kernel,
                         cudaFuncAttributeMaxDynamicSharedMemorySize, SMEM_BYTES);
    conv1x1_hmma_kernel<<<GRID, NTHREADS, SMEM_BYTES>>>(x, w, out);
}